// round 4
// baseline (speedup 1.0000x reference)
#include <cuda_runtime.h>

// DynamicMaskHead fused kernel, round 4:
//  - f32x2 lanes packed over adjacent PIXELS: no per-pixel splats
//  - per-instance weights stored DUPLICATED in smem -> LDS.128 yields two
//    weight splats per load (warp-uniform address = broadcast, conflict-free)
//  - 4 pixels/thread/iter, LDG.128 feat loads
//  - __launch_bounds__(128,5): 5 blocks/SM (occupancy over per-warp ILP)
//  - all index math strength-reduced to incremental counters (no int div)
//  - fused aligned_bilinear x2 from smem logit tile

#define WW    192
#define HH    128
#define HWSZ  (192*128)
#define CIN   8
#define TH    16
#define NROWS (TH + 1)           // +1 halo row above
#define UPR   (WW/4)             // 48 four-pixel units per row
#define NUNIT (NROWS * UPR)      // 816
#define OWW   384
#define OHH   256
#define NP    169

__device__ __forceinline__ float2 ffma2(float2 a, float2 b, float2 c) {
    float2 d;
    asm("fma.rn.f32x2 %0, %1, %2, %3;"
        : "=l"(reinterpret_cast<unsigned long long&>(d))
        : "l"(reinterpret_cast<unsigned long long&>(a)),
          "l"(reinterpret_cast<unsigned long long&>(b)),
          "l"(reinterpret_cast<unsigned long long&>(c)));
    return d;
}
__device__ __forceinline__ float2 relu2(float2 v) {
    return make_float2(fmaxf(v.x, 0.f), fmaxf(v.y, 0.f));
}
__device__ __forceinline__ float2 f2(float a, float b) { return make_float2(a, b); }

__global__ __launch_bounds__(128, 5) void dyn_mask_head_kernel(
    const float* __restrict__ mask_feats,   // [2, 8, 128, 192]
    const float* __restrict__ params,       // [n_inst, 169]
    const float* __restrict__ locs,         // [n_inst, 2] (x, y)
    const float* __restrict__ soi,          // [5]
    const int*   __restrict__ im_inds,      // [n_inst]
    const int*   __restrict__ fpn_levels,   // [n_inst]
    float*       __restrict__ out)          // [n_inst, 1, 256, 384]
{
    const int n   = blockIdx.y;
    const int r0  = blockIdx.x * TH;
    const int tid = threadIdx.x;

    // duplicated weights: every scalar stored twice -> LDS.128 = 2 splats
    __shared__ __align__(16) float sw0[8][24]; // w0..w9 dup(20) + bias dup(2) + pad
    __shared__ __align__(16) float sw1[8][20]; // w0..w7 dup(16) + bias dup(2) + pad
    __shared__ __align__(16) float sw2[20];    // w dup(16) + bias dup(2) + pad
    __shared__ __align__(16) float sL[NROWS][WW];

    {
        const float* p = params + n * NP;
        for (int t = tid; t < NP; t += 128) {
            float v = __ldg(p + t);
            if (t < 80) {
                int c = t / 10, j = t - 10 * c;
                sw0[c][2*j] = v; sw0[c][2*j+1] = v;
            } else if (t < 144) {
                int q = t - 80; int c = q >> 3, j = q & 7;
                sw1[c][2*j] = v; sw1[c][2*j+1] = v;
            } else if (t < 152) {
                int j = t - 144;
                sw2[2*j] = v; sw2[2*j+1] = v;
            } else if (t < 160) {
                int c = t - 152;
                sw0[c][20] = v; sw0[c][21] = v;
            } else if (t < 168) {
                int c = t - 160;
                sw1[c][16] = v; sw1[c][17] = v;
            } else {
                sw2[16] = v; sw2[17] = v;
            }
        }
    }
    __syncthreads();

    const int   im  = im_inds[n];
    const float inv = 1.0f / soi[fpn_levels[n]];
    const float lx  = locs[2*n + 0];
    const float ly  = locs[2*n + 1];
    const float* fb = mask_feats + (size_t)im * (CIN * HWSZ);
    const float s8  = 8.0f * inv;

    // ---- phase 1: logits, 4 consecutive pixels per thread per iter ----
    // incremental unit index: i = rl*48 + m, stride 128 = 2*48 + 32
    int rl = (tid >= 96) ? 2 : (tid >= 48 ? 1 : 0);
    int m  = tid - rl * 48;
    int cnt = tid;

#pragma unroll 1
    for (int it = 0; it < 7; it++) {
        if (cnt >= NUNIT) break;
        const int x0 = 4 * m;
        const int rc = max(r0 - 1 + rl, 0);

        const float* fp = fb + rc * WW + x0;
        float4 f[8];
#pragma unroll
        for (int k = 0; k < 8; k++)
            f[k] = *reinterpret_cast<const float4*>(fp + k * HWSZ);

        const float ryv = (ly - (float)(rc * 8 + 4)) * inv;
        const float2 ryd = f2(ryv, ryv);
        const float rxv = (lx - (float)(x0 * 8 + 4)) * inv;
        const float2 rxA = f2(rxv, rxv - s8);
        const float2 rxB = f2(rxv - 2.f * s8, rxv - 3.f * s8);

        // layer 0: 10 -> 8, relu.  A = pixels 0,1  B = pixels 2,3
        float2 hA[8], hB[8];
#pragma unroll
        for (int c = 0; c < 8; c++) {
            const float4* wc = reinterpret_cast<const float4*>(sw0[c]);
            const float2 bd = *reinterpret_cast<const float2*>(&sw0[c][20]);
            float4 w01 = wc[0];
            float2 aA = ffma2(f2(w01.x, w01.y), rxA, bd);
            float2 aB = ffma2(f2(w01.x, w01.y), rxB, bd);
            aA = ffma2(f2(w01.z, w01.w), ryd, aA);
            aB = ffma2(f2(w01.z, w01.w), ryd, aB);
#pragma unroll
            for (int kk = 0; kk < 4; kk++) {     // feats k = 2kk, 2kk+1
                float4 wp = wc[1 + kk];
                aA = ffma2(f2(wp.x, wp.y), f2(f[2*kk].x,   f[2*kk].y),   aA);
                aB = ffma2(f2(wp.x, wp.y), f2(f[2*kk].z,   f[2*kk].w),   aB);
                aA = ffma2(f2(wp.z, wp.w), f2(f[2*kk+1].x, f[2*kk+1].y), aA);
                aB = ffma2(f2(wp.z, wp.w), f2(f[2*kk+1].z, f[2*kk+1].w), aB);
            }
            hA[c] = relu2(aA);
            hB[c] = relu2(aB);
        }

        // layer 1: 8 -> 8, relu
        float2 gA[8], gB[8];
#pragma unroll
        for (int c = 0; c < 8; c++) {
            const float4* wc = reinterpret_cast<const float4*>(sw1[c]);
            const float2 bd = *reinterpret_cast<const float2*>(&sw1[c][16]);
            float2 aA = bd, aB = bd;
#pragma unroll
            for (int kk = 0; kk < 4; kk++) {
                float4 wp = wc[kk];
                aA = ffma2(f2(wp.x, wp.y), hA[2*kk],   aA);
                aB = ffma2(f2(wp.x, wp.y), hB[2*kk],   aB);
                aA = ffma2(f2(wp.z, wp.w), hA[2*kk+1], aA);
                aB = ffma2(f2(wp.z, wp.w), hB[2*kk+1], aB);
            }
            gA[c] = relu2(aA);
            gB[c] = relu2(aB);
        }

        // layer 2: 8 -> 1
        {
            const float4* wc = reinterpret_cast<const float4*>(sw2);
            const float2 bd = *reinterpret_cast<const float2*>(&sw2[16]);
            float2 oA = bd, oB = bd;
#pragma unroll
            for (int kk = 0; kk < 4; kk++) {
                float4 wp = wc[kk];
                oA = ffma2(f2(wp.x, wp.y), gA[2*kk],   oA);
                oB = ffma2(f2(wp.x, wp.y), gB[2*kk],   oB);
                oA = ffma2(f2(wp.z, wp.w), gA[2*kk+1], oA);
                oB = ffma2(f2(wp.z, wp.w), gB[2*kk+1], oB);
            }
            *reinterpret_cast<float4*>(&sL[rl][x0]) =
                make_float4(oA.x, oA.y, oB.x, oB.y);
        }

        // advance unit index by 128 = 2 rows + 32 cols
        rl += 2; m += 32;
        if (m >= 48) { m -= 48; rl += 1; }
        cnt += 128;
    }
    __syncthreads();

    // ---- phase 2: aligned_bilinear x2 from smem tile, float4 stores ----
    // out[o] = interp[max(o-1,0)]; interp[j] even -> t[j/2],
    //                               odd  -> 0.5*(t[j>>1] + t[(j>>1)+1])
    float* ob = out + (size_t)n * (OHH * OWW) + (size_t)(2 * r0) * OWW;
    // incremental group index over 32 rows x 96 col-groups; stride 128 = 96+32
    int oyl = (tid >= 96) ? 1 : 0;
    int gm  = tid - oyl * 96;
#pragma unroll 1
    for (int it = 0; it < 24; it++) {
        const int oy = 2 * r0 + oyl;
        const int iy = max(oy - 1, 0);
        const int ra = (iy >> 1) - r0 + 1;   // smem slot of row (iy>>1)

        const int cA = max(2 * gm - 1, 0);
        const int cB = 2 * gm;
        const int cC = 2 * gm + 1;

        float va, vb, vc;
        if (iy & 1) {
            va = 0.5f * (sL[ra][cA] + sL[ra + 1][cA]);
            vb = 0.5f * (sL[ra][cB] + sL[ra + 1][cB]);
            vc = 0.5f * (sL[ra][cC] + sL[ra + 1][cC]);
        } else {
            va = sL[ra][cA];
            vb = sL[ra][cB];
            vc = sL[ra][cC];
        }
        float4 o;
        o.x = 0.5f * (va + vb);   // even ox (left-edge clamp folds in at gm==0)
        o.y = vb;                 // odd ox
        o.z = 0.5f * (vb + vc);
        o.w = vc;
        *reinterpret_cast<float4*>(ob + oyl * OWW + 4 * gm) = o;

        oyl += 1; gm += 32;
        if (gm >= 96) { gm -= 96; oyl += 1; }
    }
}

extern "C" void kernel_launch(void* const* d_in, const int* in_sizes, int n_in,
                              void* d_out, int out_size) {
    const float* mask_feats = (const float*)d_in[0];
    const float* params     = (const float*)d_in[1];
    const float* locs       = (const float*)d_in[2];
    const float* soi        = (const float*)d_in[3];
    const int*   im_inds    = (const int*)d_in[4];
    const int*   fpn_levels = (const int*)d_in[5];
    float*       out        = (float*)d_out;

    const int n_inst = in_sizes[4];          // 256
    dim3 grid(HH / TH, n_inst);
    dyn_mask_head_kernel<<<grid, 128>>>(mask_feats, params, locs, soi,
                                        im_inds, fpn_levels, out);
}

// round 5
// speedup vs baseline: 1.9134x; 1.9134x over previous
#include <cuda_runtime.h>

// DynamicMaskHead fused kernel, round 5 (corrected):
//  - f32x2 lanes packed over adjacent PIXELS: no per-pixel splats
//  - duplicated weights in smem -> LDS.128 yields two weight splats (broadcast)
//  - 4 pixels/thread/iter, LDG.128 feat loads
//  - SINGLE-BUFFER software pipeline: next iteration's feats load right after
//    layer 0 consumes the current ones; layers 1-2 hide the L2 latency
//  - __launch_bounds__(128,4): regs<=128, proven no-spill (R4: 5 blocks spilled)
//  - incremental index math, no integer division
//  - fused aligned_bilinear x2 from smem logit tile

#define WW    192
#define HH    128
#define HWSZ  (192*128)
#define CIN   8
#define TH    16
#define NROWS (TH + 1)
#define UPR   (WW/4)
#define NUNIT (NROWS * UPR)      // 816
#define OWW   384
#define OHH   256
#define NP    169

__device__ __forceinline__ float2 ffma2(float2 a, float2 b, float2 c) {
    float2 d;
    asm("fma.rn.f32x2 %0, %1, %2, %3;"
        : "=l"(reinterpret_cast<unsigned long long&>(d))
        : "l"(reinterpret_cast<unsigned long long&>(a)),
          "l"(reinterpret_cast<unsigned long long&>(b)),
          "l"(reinterpret_cast<unsigned long long&>(c)));
    return d;
}
__device__ __forceinline__ float2 relu2(float2 v) {
    return make_float2(fmaxf(v.x, 0.f), fmaxf(v.y, 0.f));
}
__device__ __forceinline__ float2 f2(float a, float b) { return make_float2(a, b); }

__global__ __launch_bounds__(128, 4) void dyn_mask_head_kernel(
    const float* __restrict__ mask_feats,
    const float* __restrict__ params,
    const float* __restrict__ locs,
    const float* __restrict__ soi,
    const int*   __restrict__ im_inds,
    const int*   __restrict__ fpn_levels,
    float*       __restrict__ out)
{
    const int n   = blockIdx.y;
    const int r0  = blockIdx.x * TH;
    const int tid = threadIdx.x;

    __shared__ __align__(16) float sw0[8][24];
    __shared__ __align__(16) float sw1[8][20];
    __shared__ __align__(16) float sw2[20];
    __shared__ __align__(16) float sL[NROWS][WW];

    {
        const float* p = params + n * NP;
        for (int t = tid; t < NP; t += 128) {
            float v = __ldg(p + t);
            if (t < 80) {
                int c = t / 10, j = t - 10 * c;
                sw0[c][2*j] = v; sw0[c][2*j+1] = v;
            } else if (t < 144) {
                int q = t - 80; int c = q >> 3, j = q & 7;
                sw1[c][2*j] = v; sw1[c][2*j+1] = v;
            } else if (t < 152) {
                int j = t - 144;
                sw2[2*j] = v; sw2[2*j+1] = v;
            } else if (t < 160) {
                int c = t - 152;
                sw0[c][20] = v; sw0[c][21] = v;
            } else if (t < 168) {
                int c = t - 160;
                sw1[c][16] = v; sw1[c][17] = v;
            } else {
                sw2[16] = v; sw2[17] = v;
            }
        }
    }
    __syncthreads();

    const int   im  = im_inds[n];
    const float inv = 1.0f / soi[fpn_levels[n]];
    const float lx  = locs[2*n + 0];
    const float ly  = locs[2*n + 1];
    const float* fb = mask_feats + (size_t)im * (CIN * HWSZ);
    const float s8  = 8.0f * inv;

    int rl = (tid >= 96) ? 2 : (tid >= 48 ? 1 : 0);
    int m  = tid - rl * 48;
    int cnt = tid;

    float4 f[8];
    {
        const int rc = max(r0 - 1 + rl, 0);
        const float* fp = fb + rc * WW + 4 * m;
#pragma unroll
        for (int k = 0; k < 8; k++)
            f[k] = *reinterpret_cast<const float4*>(fp + k * HWSZ);
    }

#pragma unroll 1
    for (int it = 0; it < 7; it++) {
        if (cnt >= NUNIT) break;
        const int rl_s = rl;             // saved for the sL store
        const int x0   = 4 * m;
        const int rc   = max(r0 - 1 + rl, 0);

        const float ryv = (ly - (float)(rc * 8 + 4)) * inv;
        const float2 ryd = f2(ryv, ryv);
        const float rxv = (lx - (float)(x0 * 8 + 4)) * inv;
        const float2 rxA = f2(rxv, rxv - s8);
        const float2 rxB = f2(rxv - 2.f * s8, rxv - 3.f * s8);

        float2 hA[8], hB[8];
#pragma unroll
        for (int c = 0; c < 8; c++) {
            const float4* wc = reinterpret_cast<const float4*>(sw0[c]);
            const float2 bd = *reinterpret_cast<const float2*>(&sw0[c][20]);
            float4 w01 = wc[0];
            float2 aA = ffma2(f2(w01.x, w01.y), rxA, bd);
            float2 aB = ffma2(f2(w01.x, w01.y), rxB, bd);
            aA = ffma2(f2(w01.z, w01.w), ryd, aA);
            aB = ffma2(f2(w01.z, w01.w), ryd, aB);
#pragma unroll
            for (int kk = 0; kk < 4; kk++) {
                float4 wp = wc[1 + kk];
                aA = ffma2(f2(wp.x, wp.y), f2(f[2*kk].x,   f[2*kk].y),   aA);
                aB = ffma2(f2(wp.x, wp.y), f2(f[2*kk].z,   f[2*kk].w),   aB);
                aA = ffma2(f2(wp.z, wp.w), f2(f[2*kk+1].x, f[2*kk+1].y), aA);
                aB = ffma2(f2(wp.z, wp.w), f2(f[2*kk+1].z, f[2*kk+1].w), aB);
            }
            hA[c] = relu2(aA);
            hB[c] = relu2(aB);
        }

        // f is dead -> advance index and prefetch next unit's feats into f
        rl += 2; m += 32;
        if (m >= 48) { m -= 48; rl += 1; }
        cnt += 128;
        if (cnt < NUNIT) {
            const int rc2 = max(r0 - 1 + rl, 0);
            const float* fp2 = fb + rc2 * WW + 4 * m;
#pragma unroll
            for (int k = 0; k < 8; k++)
                f[k] = *reinterpret_cast<const float4*>(fp2 + k * HWSZ);
        }

        float2 gA[8], gB[8];
#pragma unroll
        for (int c = 0; c < 8; c++) {
            const float4* wc = reinterpret_cast<const float4*>(sw1[c]);
            const float2 bd = *reinterpret_cast<const float2*>(&sw1[c][16]);
            float2 aA = bd, aB = bd;
#pragma unroll
            for (int kk = 0; kk < 4; kk++) {
                float4 wp = wc[kk];
                aA = ffma2(f2(wp.x, wp.y), hA[2*kk],   aA);
                aB = ffma2(f2(wp.x, wp.y), hB[2*kk],   aB);
                aA = ffma2(f2(wp.z, wp.w), hA[2*kk+1], aA);
                aB = ffma2(f2(wp.z, wp.w), hB[2*kk+1], aB);
            }
            gA[c] = relu2(aA);
            gB[c] = relu2(aB);
        }

        {
            const float4* wc = reinterpret_cast<const float4*>(sw2);
            const float2 bd = *reinterpret_cast<const float2*>(&sw2[16]);
            float2 oA = bd, oB = bd;
#pragma unroll
            for (int kk = 0; kk < 4; kk++) {
                float4 wp = wc[kk];
                oA = ffma2(f2(wp.x, wp.y), gA[2*kk],   oA);
                oB = ffma2(f2(wp.x, wp.y), gB[2*kk],   oB);
                oA = ffma2(f2(wp.z, wp.w), gA[2*kk+1], oA);
                oB = ffma2(f2(wp.z, wp.w), gB[2*kk+1], oB);
            }
            *reinterpret_cast<float4*>(&sL[rl_s][x0]) =
                make_float4(oA.x, oA.y, oB.x, oB.y);
        }
    }
    __syncthreads();

    float* ob = out + (size_t)n * (OHH * OWW) + (size_t)(2 * r0) * OWW;
    int oyl = (tid >= 96) ? 1 : 0;
    int gm  = tid - oyl * 96;
#pragma unroll 1
    for (int it = 0; it < 24; it++) {
        const int oy = 2 * r0 + oyl;
        const int iy = max(oy - 1, 0);
        const int ra = (iy >> 1) - r0 + 1;

        const int cA = max(2 * gm - 1, 0);
        const int cB = 2 * gm;
        const int cC = 2 * gm + 1;

        float va, vb, vc;
        if (iy & 1) {
            va = 0.5f * (sL[ra][cA] + sL[ra + 1][cA]);
            vb = 0.5f * (sL[ra][cB] + sL[ra + 1][cB]);
            vc = 0.5f * (sL[ra][cC] + sL[ra + 1][cC]);
        } else {
            va = sL[ra][cA];
            vb = sL[ra][cB];
            vc = sL[ra][cC];
        }
        float4 o;
        o.x = 0.5f * (va + vb);
        o.y = vb;
        o.z = 0.5f * (vb + vc);
        o.w = vc;
        *reinterpret_cast<float4*>(ob + oyl * OWW + 4 * gm) = o;

        oyl += 1; gm += 32;
        if (gm >= 96) { gm -= 96; oyl += 1; }
    }
}

extern "C" void kernel_launch(void* const* d_in, const int* in_sizes, int n_in,
                              void* d_out, int out_size) {
    const float* mask_feats = (const float*)d_in[0];
    const float* params     = (const float*)d_in[1];
    const float* locs       = (const float*)d_in[2];
    const float* soi        = (const float*)d_in[3];
    const int*   im_inds    = (const int*)d_in[4];
    const int*   fpn_levels = (const int*)d_in[5];
    float*       out        = (float*)d_out;

    const int n_inst = in_sizes[4];
    dim3 grid(HH / TH, n_inst);
    dyn_mask_head_kernel<<<grid, 128>>>(mask_feats, params, locs, soi,
                                        im_inds, fpn_levels, out);
}

// round 6
// speedup vs baseline: 4.2304x; 2.2110x over previous
#include <cuda_runtime.h>

// DynamicMaskHead fused kernel, round 6:
//  - f32x2 lanes packed over adjacent PIXELS: no per-pixel splats
//  - duplicated weights in smem -> LDS gives ready weight splats (broadcast)
//  - feats staged through a cp.async (LDGSTS) DOUBLE BUFFER in shared memory:
//    zero register cost, per-thread producer==consumer so no __syncthreads,
//    latency hidden across a full iteration via cp.async.wait_group 1
//  - layer 0 consumes feats straight from smem (kk-outer/c-inner), so no
//    32-register feat block is ever live -> peak ~100 regs, no spills
//  - incremental index math, no integer division
//  - fused aligned_bilinear x2 from smem logit tile

#define WW    192
#define HH    128
#define HWSZ  (192*128)
#define CIN   8
#define TH    16
#define NROWS (TH + 1)
#define UPR   (WW/4)
#define NUNIT (NROWS * UPR)      // 816
#define OWW   384
#define OHH   256
#define NP    169

__device__ __forceinline__ float2 ffma2(float2 a, float2 b, float2 c) {
    float2 d;
    asm("fma.rn.f32x2 %0, %1, %2, %3;"
        : "=l"(reinterpret_cast<unsigned long long&>(d))
        : "l"(reinterpret_cast<unsigned long long&>(a)),
          "l"(reinterpret_cast<unsigned long long&>(b)),
          "l"(reinterpret_cast<unsigned long long&>(c)));
    return d;
}
__device__ __forceinline__ float2 relu2(float2 v) {
    return make_float2(fmaxf(v.x, 0.f), fmaxf(v.y, 0.f));
}
__device__ __forceinline__ float2 f2(float a, float b) { return make_float2(a, b); }

__device__ __forceinline__ void cpasync16(void* dst, const void* src) {
    unsigned sdst = (unsigned)__cvta_generic_to_shared(dst);
    asm volatile("cp.async.cg.shared.global [%0], [%1], 16;"
                 :: "r"(sdst), "l"(src));
}
#define CP_COMMIT() asm volatile("cp.async.commit_group;" ::: "memory")
#define CP_WAIT1()  asm volatile("cp.async.wait_group 1;" ::: "memory")

__global__ __launch_bounds__(128, 4) void dyn_mask_head_kernel(
    const float* __restrict__ mask_feats,   // [2, 8, 128, 192]
    const float* __restrict__ params,       // [n_inst, 169]
    const float* __restrict__ locs,         // [n_inst, 2] (x, y)
    const float* __restrict__ soi,          // [5]
    const int*   __restrict__ im_inds,      // [n_inst]
    const int*   __restrict__ fpn_levels,   // [n_inst]
    float*       __restrict__ out)          // [n_inst, 1, 256, 384]
{
    const int n   = blockIdx.y;
    const int r0  = blockIdx.x * TH;
    const int tid = threadIdx.x;

    __shared__ __align__(16) float sw0[8][24]; // w0..w9 dup(20) + bias dup(2) + pad
    __shared__ __align__(16) float sw1[8][20]; // w0..w7 dup(16) + bias dup(2) + pad
    __shared__ __align__(16) float sw2[20];
    __shared__ __align__(16) float sL[NROWS][WW];
    __shared__ __align__(16) float4 sF[2][8][128];   // cp.async feat stages

    {
        const float* p = params + n * NP;
        for (int t = tid; t < NP; t += 128) {
            float v = __ldg(p + t);
            if (t < 80) {
                int c = t / 10, j = t - 10 * c;
                sw0[c][2*j] = v; sw0[c][2*j+1] = v;
            } else if (t < 144) {
                int q = t - 80; int c = q >> 3, j = q & 7;
                sw1[c][2*j] = v; sw1[c][2*j+1] = v;
            } else if (t < 152) {
                int j = t - 144;
                sw2[2*j] = v; sw2[2*j+1] = v;
            } else if (t < 160) {
                int c = t - 152;
                sw0[c][20] = v; sw0[c][21] = v;
            } else if (t < 168) {
                int c = t - 160;
                sw1[c][16] = v; sw1[c][17] = v;
            } else {
                sw2[16] = v; sw2[17] = v;
            }
        }
    }
    __syncthreads();

    const int   im  = im_inds[n];
    const float inv = 1.0f / soi[fpn_levels[n]];
    const float lx  = locs[2*n + 0];
    const float ly  = locs[2*n + 1];
    const float* fb = mask_feats + (size_t)im * (CIN * HWSZ);
    const float s8  = 8.0f * inv;

    // unit index i = rl*48 + m; per-iter stride 128 = 2 rows + 32 cols
    int rl = (tid >= 96) ? 2 : (tid >= 48 ? 1 : 0);
    int m  = tid - rl * 48;
    int cnt = tid;

    // stage 0: issue cp.async for this thread's first unit
    {
        const int rc = max(r0 - 1 + rl, 0);
        const float* fp = fb + rc * WW + 4 * m;
#pragma unroll
        for (int k = 0; k < 8; k++)
            cpasync16(&sF[0][k][tid], fp + k * HWSZ);
    }
    CP_COMMIT();

    int stage = 0;
#pragma unroll 1
    for (int it = 0; it < 7; it++) {
        if (cnt >= NUNIT) break;
        const int rl_s = rl;
        const int x0   = 4 * m;
        const int rc   = max(r0 - 1 + rl, 0);

        // prefetch next unit into the other stage (no registers held)
        int rl2 = rl + 2, m2 = m + 32;
        if (m2 >= 48) { m2 -= 48; rl2 += 1; }
        const int cnt2 = cnt + 128;
        if (cnt2 < NUNIT) {
            const int rc2 = max(r0 - 1 + rl2, 0);
            const float* fp2 = fb + rc2 * WW + 4 * m2;
#pragma unroll
            for (int k = 0; k < 8; k++)
                cpasync16(&sF[stage ^ 1][k][tid], fp2 + k * HWSZ);
        }
        CP_COMMIT();
        CP_WAIT1();   // current stage's group (older) is now complete

        const float ryv = (ly - (float)(rc * 8 + 4)) * inv;
        const float2 ryd = f2(ryv, ryv);
        const float rxv = (lx - (float)(x0 * 8 + 4)) * inv;
        const float2 rxA = f2(rxv, rxv - s8);
        const float2 rxB = f2(rxv - 2.f * s8, rxv - 3.f * s8);

        // ---- layer 0: 10 -> 8, relu. kk-outer / c-inner, feats from smem ----
        float2 aA[8], aB[8];
#pragma unroll
        for (int c = 0; c < 8; c++) {
            const float4 w01 = *reinterpret_cast<const float4*>(sw0[c]);
            const float2 bd  = *reinterpret_cast<const float2*>(&sw0[c][20]);
            aA[c] = ffma2(f2(w01.x, w01.y), rxA, bd);
            aB[c] = ffma2(f2(w01.x, w01.y), rxB, bd);
            aA[c] = ffma2(f2(w01.z, w01.w), ryd, aA[c]);
            aB[c] = ffma2(f2(w01.z, w01.w), ryd, aB[c]);
        }
#pragma unroll
        for (int kk = 0; kk < 4; kk++) {     // feats k = 2kk, 2kk+1
            const float2* fp0 = reinterpret_cast<const float2*>(&sF[stage][2*kk][tid]);
            const float2* fp1 = reinterpret_cast<const float2*>(&sF[stage][2*kk+1][tid]);
            const float2 fA0 = fp0[0], fB0 = fp0[1];
            const float2 fA1 = fp1[0], fB1 = fp1[1];
#pragma unroll
            for (int c = 0; c < 8; c++) {
                const float4 wp = *reinterpret_cast<const float4*>(&sw0[c][4 + 4*kk]);
                aA[c] = ffma2(f2(wp.x, wp.y), fA0, aA[c]);
                aB[c] = ffma2(f2(wp.x, wp.y), fB0, aB[c]);
                aA[c] = ffma2(f2(wp.z, wp.w), fA1, aA[c]);
                aB[c] = ffma2(f2(wp.z, wp.w), fB1, aB[c]);
            }
        }
        float2 hA[8], hB[8];
#pragma unroll
        for (int c = 0; c < 8; c++) { hA[c] = relu2(aA[c]); hB[c] = relu2(aB[c]); }

        // ---- layer 1: 8 -> 8, relu ----
        float2 gA[8], gB[8];
#pragma unroll
        for (int c = 0; c < 8; c++) {
            const float4* wc = reinterpret_cast<const float4*>(sw1[c]);
            const float2 bd = *reinterpret_cast<const float2*>(&sw1[c][16]);
            float2 tA = bd, tB = bd;
#pragma unroll
            for (int kk = 0; kk < 4; kk++) {
                const float4 wp = wc[kk];
                tA = ffma2(f2(wp.x, wp.y), hA[2*kk],   tA);
                tB = ffma2(f2(wp.x, wp.y), hB[2*kk],   tB);
                tA = ffma2(f2(wp.z, wp.w), hA[2*kk+1], tA);
                tB = ffma2(f2(wp.z, wp.w), hB[2*kk+1], tB);
            }
            gA[c] = relu2(tA);
            gB[c] = relu2(tB);
        }

        // ---- layer 2: 8 -> 1 ----
        {
            const float4* wc = reinterpret_cast<const float4*>(sw2);
            const float2 bd = *reinterpret_cast<const float2*>(&sw2[16]);
            float2 oA = bd, oB = bd;
#pragma unroll
            for (int kk = 0; kk < 4; kk++) {
                const float4 wp = wc[kk];
                oA = ffma2(f2(wp.x, wp.y), gA[2*kk],   oA);
                oB = ffma2(f2(wp.x, wp.y), gB[2*kk],   oB);
                oA = ffma2(f2(wp.z, wp.w), gA[2*kk+1], oA);
                oB = ffma2(f2(wp.z, wp.w), gB[2*kk+1], oB);
            }
            *reinterpret_cast<float4*>(&sL[rl_s][x0]) =
                make_float4(oA.x, oA.y, oB.x, oB.y);
        }

        rl = rl2; m = m2; cnt = cnt2; stage ^= 1;
    }
    __syncthreads();

    // ---- phase 2: aligned_bilinear x2 from smem tile, float4 stores ----
    float* ob = out + (size_t)n * (OHH * OWW) + (size_t)(2 * r0) * OWW;
    int oyl = (tid >= 96) ? 1 : 0;
    int gm  = tid - oyl * 96;
#pragma unroll 1
    for (int it = 0; it < 24; it++) {
        const int oy = 2 * r0 + oyl;
        const int iy = max(oy - 1, 0);
        const int ra = (iy >> 1) - r0 + 1;

        const int cA = max(2 * gm - 1, 0);
        const int cB = 2 * gm;
        const int cC = 2 * gm + 1;

        float va, vb, vc;
        if (iy & 1) {
            va = 0.5f * (sL[ra][cA] + sL[ra + 1][cA]);
            vb = 0.5f * (sL[ra][cB] + sL[ra + 1][cB]);
            vc = 0.5f * (sL[ra][cC] + sL[ra + 1][cC]);
        } else {
            va = sL[ra][cA];
            vb = sL[ra][cB];
            vc = sL[ra][cC];
        }
        float4 o;
        o.x = 0.5f * (va + vb);
        o.y = vb;
        o.z = 0.5f * (vb + vc);
        o.w = vc;
        *reinterpret_cast<float4*>(ob + oyl * OWW + 4 * gm) = o;

        oyl += 1; gm += 32;
        if (gm >= 96) { gm -= 96; oyl += 1; }
    }
}

extern "C" void kernel_launch(void* const* d_in, const int* in_sizes, int n_in,
                              void* d_out, int out_size) {
    const float* mask_feats = (const float*)d_in[0];
    const float* params     = (const float*)d_in[1];
    const float* locs       = (const float*)d_in[2];
    const float* soi        = (const float*)d_in[3];
    const int*   im_inds    = (const int*)d_in[4];
    const int*   fpn_levels = (const int*)d_in[5];
    float*       out        = (float*)d_out;

    const int n_inst = in_sizes[4];
    dim3 grid(HH / TH, n_inst);
    dyn_mask_head_kernel<<<grid, 128>>>(mask_feats, params, locs, soi,
                                        im_inds, fpn_levels, out);
}